// round 3
// baseline (speedup 1.0000x reference)
#include <cuda_runtime.h>
#include <cstdint>

// x: [B=16, C=8, T=262144] fp32 row-major.
// out = x * (c == 0 ? 1.0f : 0.5f)
// float4 index i: channel = (i >> 16) & 7   (T/4 = 2^16 float4 per channel row).
//
// STRIDE = 2^20 float4s => (k*STRIDE >> 16) & 7 == 0 for all k, so every
// vector a thread touches lives in the SAME channel: one scale per thread.

static constexpr long long N_ELEMS = 16LL * 8LL * 262144LL;   // 33,554,432
static constexpr long long N_VEC4  = N_ELEMS / 4;             // 8,388,608 = 2^23
static constexpr int       UNROLL  = 8;
static constexpr long long STRIDE  = N_VEC4 / UNROLL;         // 1,048,576 = 2^20
static constexpr int       THREADS = 256;
static constexpr int       BLOCKS  = (int)(STRIDE / THREADS); // 4096, exact

__global__ void __launch_bounds__(THREADS) channel_scale_kernel(
    const float4* __restrict__ x, float4* __restrict__ out)
{
    const long long i0 = (long long)blockIdx.x * THREADS + threadIdx.x;

    // One channel select for all 8 vectors handled by this thread.
    const float s = ((i0 & (7LL << 16)) == 0) ? 1.0f : 0.5f;

    // Front-batch 8 independent 128-bit streaming loads (per-thread MLP=8).
    float4 v[UNROLL];
#pragma unroll
    for (int k = 0; k < UNROLL; k++) {
        v[k] = __ldcs(&x[i0 + (long long)k * STRIDE]);
    }

#pragma unroll
    for (int k = 0; k < UNROLL; k++) {
        float4 w = v[k];
        w.x *= s; w.y *= s; w.z *= s; w.w *= s;
        __stcs(&out[i0 + (long long)k * STRIDE], w);
    }
}

extern "C" void kernel_launch(void* const* d_in, const int* in_sizes, int n_in,
                              void* d_out, int out_size)
{
    const float4* x = (const float4*)d_in[0];
    float4* out = (float4*)d_out;
    channel_scale_kernel<<<BLOCKS, THREADS>>>(x, out);
}

// round 4
// speedup vs baseline: 1.0280x; 1.0280x over previous
#include <cuda_runtime.h>
#include <cstdint>

// x: [B=16, C=8, T=262144] fp32 row-major.
// out = x * (c == 0 ? 1.0f : 0.5f)
//
// Block-contiguous tiling: each block handles 2048 consecutive float4s (32 KB).
// Channel row = T/4 = 65536 float4s; 65536 % 2048 == 0, so every tile lies
// entirely inside one channel -> scale is uniform per block:
//   channel = (blockIdx.x * 2048 >> 16) & 7 = (blockIdx.x >> 5) & 7.

static constexpr long long N_VEC4  = (16LL * 8LL * 262144LL) / 4;  // 8,388,608 = 2^23
static constexpr int       THREADS = 512;
static constexpr int       UNROLL  = 4;
static constexpr int       TILE    = THREADS * UNROLL;             // 2048 float4s
static constexpr int       BLOCKS  = (int)(N_VEC4 / TILE);         // 4096, exact

__global__ void __launch_bounds__(THREADS) channel_scale_kernel(
    const float4* __restrict__ x, float4* __restrict__ out)
{
    // Per-block uniform channel scale (bits [5:8) of blockIdx select channel).
    const float s = ((blockIdx.x & (7u << 5)) == 0u) ? 1.0f : 0.5f;

    const long long base = (long long)blockIdx.x * TILE + threadIdx.x;

    float4 v[UNROLL];
#pragma unroll
    for (int k = 0; k < UNROLL; k++) {
        v[k] = __ldcs(&x[base + k * THREADS]);
    }

#pragma unroll
    for (int k = 0; k < UNROLL; k++) {
        float4 w = v[k];
        w.x *= s; w.y *= s; w.z *= s; w.w *= s;
        __stcs(&out[base + k * THREADS], w);
    }
}

extern "C" void kernel_launch(void* const* d_in, const int* in_sizes, int n_in,
                              void* d_out, int out_size)
{
    const float4* x = (const float4*)d_in[0];
    float4* out = (float4*)d_out;
    channel_scale_kernel<<<BLOCKS, THREADS>>>(x, out);
}